// round 10
// baseline (speedup 1.0000x reference)
#include <cuda_runtime.h>
#include <cstdint>

// out[b,i,j] = x[b, i, i+j] if i+j < L else 0
// B=4, L=4096, LIMIT=256
#define MAXLEN 4096
#define LIMIT  256
#define BATCH  4

#define NROWS     (BATCH * MAXLEN)     // 16384
#define NSM       148
#define OCC       8
#define NBLOCKS   (NSM * OCC)          // 1184 CTAs (single wave)
#define TPB       256                  // 8 warps; warp handles one row per trip
#define ROWSTRIDE (NBLOCKS * (TPB/32)) // 9472 rows per sweep
#define FULLM     0xFFFFFFFFu

// 256-bit load/store with L2 evict_last (the only forms ptxas accepts the
// modifier on for sm_103a). Band + output (~35MB) << 126MB L2 -> pin so graph
// replays hit L2 instead of DRAM.
__device__ __forceinline__ void ld8_el(uint32_t* d, const float* p) {
    asm("ld.global.nc.L2::evict_last.v8.b32 {%0,%1,%2,%3,%4,%5,%6,%7}, [%8];"
        : "=r"(d[0]), "=r"(d[1]), "=r"(d[2]), "=r"(d[3]),
          "=r"(d[4]), "=r"(d[5]), "=r"(d[6]), "=r"(d[7])
        : "l"(p));
}
__device__ __forceinline__ void st8_el(float* p, const uint32_t* s) {
    asm volatile(
        "st.global.L2::evict_last.v8.b32 [%0], {%1,%2,%3,%4,%5,%6,%7,%8};"
        :: "l"(p),
           "r"(s[0]), "r"(s[1]), "r"(s[2]), "r"(s[3]),
           "r"(s[4]), "r"(s[5]), "r"(s[6]), "r"(s[7])
        : "memory");
}

template <int A>
__device__ __forceinline__ void shift_sel(uint32_t* v, const uint32_t* D0,
                                          const uint32_t* D1) {
    #pragma unroll
    for (int k = 0; k < 8; k++)
        v[k] = (k + A < 8) ? D0[k + A] : D1[k + A - 8];
}

__device__ __forceinline__ void do_row(const float* __restrict__ x,
                                       float* __restrict__ out,
                                       int row, int lane)
{
    const int i   = row & (MAXLEN - 1);
    const int a   = i & 7;                   // misalignment in floats (uniform)
    const int b8  = i >> 3;                  // first aligned 32B block
    const int lim = MAXLEN - i;              // j < lim is valid
    const float* __restrict__ xr = x + ((size_t)row << 12);
    float* __restrict__ orow = out + ((size_t)row << 8);

    // Lane loads its 32B block once; one extra block broadcast for the seam.
    uint32_t D0[8], E[8], D1[8], v[8];
    ld8_el(D0, xr + ((size_t)min(b8 + lane, 511) << 3));
    ld8_el(E,  xr + ((size_t)min(b8 + 32,   511) << 3));

    #pragma unroll
    for (int k = 0; k < 8; k++)
        D1[k] = __shfl_down_sync(FULLM, D0[k], 1);
    if (lane == 31) {
        #pragma unroll
        for (int k = 0; k < 8; k++) D1[k] = E[k];
    }

    switch (a) {                             // warp-uniform branch
        case 0: shift_sel<0>(v, D0, D1); break;
        case 1: shift_sel<1>(v, D0, D1); break;
        case 2: shift_sel<2>(v, D0, D1); break;
        case 3: shift_sel<3>(v, D0, D1); break;
        case 4: shift_sel<4>(v, D0, D1); break;
        case 5: shift_sel<5>(v, D0, D1); break;
        case 6: shift_sel<6>(v, D0, D1); break;
        default: shift_sel<7>(v, D0, D1); break;
    }

    const int j0 = lane << 3;                // first j of this lane's block
    if (j0 + 7 >= lim) {                     // rare tail rows only
        #pragma unroll
        for (int k = 0; k < 8; k++)
            if (j0 + k >= lim) v[k] = 0u;
    }

    st8_el(orow + j0, v);
}

__global__ __launch_bounds__(TPB)
void band_gather_kernel(const float* __restrict__ x, float* __restrict__ out)
{
    const int lane = threadIdx.x & 31;
    const int warp = blockIdx.x * (TPB / 32) + (threadIdx.x >> 5);

    do_row(x, out, warp, lane);              // rows 0..9471

    const int row2 = warp + ROWSTRIDE;       // rows 9472..16383
    if (row2 < NROWS)
        do_row(x, out, row2, lane);
}

extern "C" void kernel_launch(void* const* d_in, const int* in_sizes, int n_in,
                              void* d_out, int out_size)
{
    (void)in_sizes; (void)n_in; (void)out_size;
    const float* x = (const float*)d_in[0];
    float* out = (float*)d_out;
    band_gather_kernel<<<NBLOCKS, TPB>>>(x, out);
}

// round 11
// speedup vs baseline: 1.0295x; 1.0295x over previous
#include <cuda_runtime.h>
#include <cstdint>

// out[b,i,j] = x[b, i, i+j] if i+j < L else 0
// B=4, L=4096, LIMIT=256
#define MAXLEN 4096
#define LIMIT  256
#define BATCH  4

#define NROWS    (BATCH * MAXLEN)  // 16384
#define RPC      16                // rows per CTA
#define SPC      2                 // pipeline stages
#define RPS      (RPC / SPC)       // 8 rows per stage
#define TPB      256               // 8 warps: one row per warp per stage
#define NBLOCKS  (NROWS / RPC)     // 1024
#define SLOT_B   1056              // 65 f4 data + pad

__device__ __forceinline__ uint32_t smem_u32(const void* p) {
    uint32_t a;
    asm("{ .reg .u64 t; cvta.to.shared.u64 t, %1; cvt.u32.u64 %0, t; }"
        : "=r"(a) : "l"(p));
    return a;
}

__device__ __forceinline__ void mbar_wait0(uint32_t mb) {
    uint32_t done;
    asm volatile(
        "{\n\t.reg .pred p;\n\t"
        "mbarrier.try_wait.parity.acquire.cta.shared::cta.b64 p, [%1], 0;\n\t"
        "selp.b32 %0, 1, 0, p;\n\t}"
        : "=r"(done) : "r"(mb) : "memory");
    if (!done) {
        asm volatile(
            "{\n\t.reg .pred P1;\n\t"
            "WL_%=:\n\t"
            "mbarrier.try_wait.parity.acquire.cta.shared::cta.b64 P1, [%0], 0, 0x989680;\n\t"
            "@P1 bra.uni WD_%=;\n\t"
            "bra.uni WL_%=;\n\t"
            "WD_%=:\n\t}"
            :: "r"(mb) : "memory");
    }
}

__global__ __launch_bounds__(TPB)
void band_gather_kernel(const float* __restrict__ x, float* __restrict__ out)
{
    __shared__ __align__(16) unsigned char buf[RPC * SLOT_B];
    __shared__ __align__(8)  uint64_t mbar[SPC];

    const int tid  = threadIdx.x;
    const int lane = tid & 31;
    const int wrp  = tid >> 5;

    if (tid < SPC) {
        asm volatile("mbarrier.init.shared.b64 [%0], %1;"
                     :: "r"(smem_u32(&mbar[tid])), "r"(RPS) : "memory");
    }
    __syncthreads();

    // ---- Issue ALL bulk reads up-front (16 rows; threads 0..15, one each) ----
    if (tid < RPC) {
        const int s   = tid >> 3;                  // stage
        const int row = blockIdx.x * RPC + tid;    // b*L + i
        const int i   = row & (MAXLEN - 1);
        const int a0  = i & ~3;                    // 16B-aligned start col
        const uint32_t bytes =
            min((uint32_t)1040u, (uint32_t)((MAXLEN - a0) * 4));
        const float* src = x + ((size_t)row << 12) + a0;
        const uint32_t dst = smem_u32(buf) + tid * SLOT_B;
        const uint32_t mb  = smem_u32(&mbar[s]);

        asm volatile("mbarrier.arrive.expect_tx.shared.b64 _, [%0], %1;"
                     :: "r"(mb), "r"(bytes) : "memory");
        asm volatile(
            "cp.async.bulk.shared::cluster.global.mbarrier::complete_tx::bytes "
            "[%0], [%1], %2, [%3];"
            :: "r"(dst), "l"(src), "r"(bytes), "r"(mb) : "memory");
    }

    // ---- Drain stage by stage; each warp owns one row per stage ----
    #pragma unroll
    for (int s = 0; s < SPC; s++) {
        mbar_wait0(smem_u32(&mbar[s]));

        const int r_loc = s * RPS + wrp;
        const int row   = blockIdx.x * RPC + r_loc;
        const int i     = row & (MAXLEN - 1);
        const int a     = i & 3;                   // shift (warp-uniform)
        const int lim   = MAXLEN - i;              // j < lim valid

        const float4* sl =
            reinterpret_cast<const float4*>(buf + r_loc * SLOT_B);
        float4* orow = reinterpret_cast<float4*>(out) + ((size_t)row << 6);

        #pragma unroll
        for (int it = 0; it < 2; it++) {
            const int o  = lane + it * 32;         // output f4 index 0..63
            const float4 w0 = sl[o];
            const float4 w1 = sl[o + 1];

            float4 v;                              // funnel shift by a floats
            if      (a == 0) { v.x = w0.x; v.y = w0.y; v.z = w0.z; v.w = w0.w; }
            else if (a == 1) { v.x = w0.y; v.y = w0.z; v.z = w0.w; v.w = w1.x; }
            else if (a == 2) { v.x = w0.z; v.y = w0.w; v.z = w1.x; v.w = w1.y; }
            else             { v.x = w0.w; v.y = w1.x; v.z = w1.y; v.w = w1.z; }

            const int j0 = o << 2;
            if (j0 + 3 >= lim) {                   // tail rows only
                if (j0 + 0 >= lim) v.x = 0.0f;
                if (j0 + 1 >= lim) v.y = 0.0f;
                if (j0 + 2 >= lim) v.z = 0.0f;
                if (j0 + 3 >= lim) v.w = 0.0f;
            }
            orow[o] = v;
        }
    }
}

extern "C" void kernel_launch(void* const* d_in, const int* in_sizes, int n_in,
                              void* d_out, int out_size)
{
    (void)in_sizes; (void)n_in; (void)out_size;
    const float* x = (const float*)d_in[0];
    float* out = (float*)d_out;
    band_gather_kernel<<<NBLOCKS, TPB>>>(x, out);
}